// round 14
// baseline (speedup 1.0000x reference)
#include <cuda_runtime.h>
#include <cuda_fp16.h>
#include <cstdint>

#define BATCH 8
#define TLEN 4096
#define INDIM 128
#define OUTDIM 128
#define HID 256
#define NSTAGE 3
// gemm1 tiles (256 threads, 128t x 128m)
#define PITCH_H 136
#define KC 32
#define BBUF_H (KC * PITCH_H)
#define WFRAG 2048
#define SMEM_G1 (NSTAGE * (BBUF_H * 2 + WFRAG * 4))   // 50688
// gemm2 tiles (128 threads, 64t x 128o)
#define PITCH2_H 72
#define BBUF2_H (KC * PITCH2_H)                        // 2304 halves
#define SMEM_G2 (NSTAGE * (BBUF2_H * 2 + WFRAG * 4))   // 38400

// ---- scratch (device globals: allocation-free rule) ----
__device__ float g_lam_re[HID];
__device__ float g_lam_im[HID];
__device__ float g_mag[HID];
__device__ float g_th[HID];
__device__ __half g_bx_re[(size_t)BATCH * HID * TLEN];   // [b][h][t] fp16
__device__ __half g_bx_im[(size_t)BATCH * HID * TLEN];
__device__ __half g_xt[(size_t)BATCH * INDIM * TLEN];    // [b][i][t] fp16
// fp16 weight fragments, mma m16n8k16 order: [K16][mt][lane][4 words]
__device__ unsigned g_wf1h[8 * 32 * 32 * 4];             // gemm1: M=512, K=128
__device__ unsigned g_wf2h[40 * 8 * 32 * 4];             // gemm2: M=128, K=640

// ---- helpers ----
__device__ __forceinline__ unsigned pack_h2(float lo, float hi) {
    unsigned d;
    asm("cvt.rn.f16x2.f32 %0, %1, %2;" : "=r"(d) : "f"(hi), "f"(lo));
    return d;
}
__device__ __forceinline__ void mma16(float& d0, float& d1, float& d2, float& d3,
                                      unsigned a0, unsigned a1, unsigned a2, unsigned a3,
                                      unsigned b0, unsigned b1) {
    asm("mma.sync.aligned.m16n8k16.row.col.f32.f16.f16.f32 "
        "{%0,%1,%2,%3}, {%4,%5,%6,%7}, {%8,%9}, {%0,%1,%2,%3};"
        : "+f"(d0), "+f"(d1), "+f"(d2), "+f"(d3)
        : "r"(a0), "r"(a1), "r"(a2), "r"(a3), "r"(b0), "r"(b1));
}
__device__ __forceinline__ void ldsm4t(unsigned& r0, unsigned& r1,
                                       unsigned& r2, unsigned& r3, unsigned addr) {
    asm volatile("ldmatrix.sync.aligned.m8n8.x4.trans.shared.b16 {%0,%1,%2,%3}, [%4];"
        : "=r"(r0), "=r"(r1), "=r"(r2), "=r"(r3) : "r"(addr));
}
__device__ __forceinline__ unsigned smem_u32(const void* p) {
    return (unsigned)__cvta_generic_to_shared(p);
}
__device__ __forceinline__ void cp16(unsigned s, const void* g) {
    asm volatile("cp.async.cg.shared.global [%0], [%1], 16;" :: "r"(s), "l"(g));
}
__device__ __forceinline__ void cp_commit() { asm volatile("cp.async.commit_group;"); }
__device__ __forceinline__ void cp_wait1()  { asm volatile("cp.async.wait_group 1;"); }
__device__ __forceinline__ void cp_wait0()  { asm volatile("cp.async.wait_group 0;"); }

// ---------------------------------------------------------------------------
// prep_all: X transpose (fp16 packed) + fp16 weight fragments + params
// ---------------------------------------------------------------------------
#define WF1H_N (8 * 32 * 32 * 4)    // 32768 words
#define WF2H_N (40 * 8 * 32 * 4)    // 40960 words
#define NB_XT 4096
#define NB_W  ((WF1H_N + WF2H_N) / 256)   // 288
#define NB_ALL (NB_XT + NB_W + 1)

__global__ __launch_bounds__(256)
void prep_all_kernel(const float* __restrict__ X,
                     const float* __restrict__ nu_log,
                     const float* __restrict__ theta_log,
                     const float* __restrict__ Bre, const float* __restrict__ Bim,
                     const float* __restrict__ Cre, const float* __restrict__ Cim,
                     const float* __restrict__ Dm) {
    __shared__ float tile[32][33];
    int bid = blockIdx.x;
    int tid = threadIdx.x;

    if (bid < NB_XT) {
        int t0 = (bid & 127) * 32;
        int i0 = ((bid >> 7) & 3) * 32;
        int b  = bid >> 9;
#pragma unroll
        for (int r = 0; r < 4; r++) {
            int idx = tid + 256 * r;
            int tl = idx >> 5, il = idx & 31;
            tile[tl][il] = X[((size_t)b * TLEN + t0 + tl) * INDIM + i0 + il];
        }
        __syncthreads();
#pragma unroll
        for (int r = 0; r < 2; r++) {
            int idx = tid + 256 * r;
            int il = idx >> 4, tp = idx & 15;
            unsigned w = pack_h2(tile[2 * tp][il], tile[2 * tp + 1][il]);
            ((unsigned*)g_xt)[(((size_t)b * INDIM + i0 + il) * TLEN + t0) / 2 + tp] = w;
        }
    } else if (bid < NB_XT + NB_W) {
        int idx = (bid - NB_XT) * 256 + tid;
        if (idx < WF1H_N) {
            int j = idx & 3, lane = (idx >> 2) & 31, mt = (idx >> 7) & 31, K16 = idx >> 12;
            int g = lane >> 2, tig = lane & 3;
            int m = mt * 16 + g + (j & 1) * 8;
            int k0 = K16 * 16 + 2 * tig + (j >> 1) * 8;
            int h = m & 255;
            float mag = expf(-expf(nu_log[h]));
            float gam = sqrtf(fmaxf(1.0f - mag * mag, 0.0f));
            const float* wrow = (m < 256) ? &Bre[(size_t)h * INDIM] : &Bim[(size_t)h * INDIM];
            g_wf1h[idx] = pack_h2(gam * wrow[k0], gam * wrow[k0 + 1]);
        } else {
            int e = idx - WF1H_N;
            int j = e & 3, lane = (e >> 2) & 31, mt = (e >> 7) & 7, K16 = e >> 10;
            int g = lane >> 2, tig = lane & 3;
            int o = mt * 16 + g + (j & 1) * 8;
            int k0 = K16 * 16 + 2 * tig + (j >> 1) * 8;
            float v0, v1;
            if (k0 < 256)      { v0 =  Cre[(size_t)o * HID + k0];         v1 =  Cre[(size_t)o * HID + k0 + 1]; }
            else if (k0 < 512) { v0 = -Cim[(size_t)o * HID + k0 - 256];   v1 = -Cim[(size_t)o * HID + k0 - 255]; }
            else               { v0 =  Dm[(size_t)o * INDIM + k0 - 512];  v1 =  Dm[(size_t)o * INDIM + k0 - 511]; }
            g_wf2h[e] = pack_h2(v0, v1);
        }
    } else {
        int h = tid;
        if (h < HID) {
            float mag = expf(-expf(nu_log[h]));
            float th  = expf(theta_log[h]);
            g_mag[h] = mag;
            g_th[h]  = th;
            g_lam_re[h] = mag * cosf(th);
            g_lam_im[h] = mag * sinf(th);
        }
    }
}

// ---------------------------------------------------------------------------
// GEMM1 (256 threads, tile 128m x 128t, 3 CTAs/SM via launch_bounds)
// ---------------------------------------------------------------------------
__device__ __forceinline__ void g1_fill_b(__half* Bsh, int buf, const __half* arow,
                                          int row, int cq) {
    unsigned sb = smem_u32(&Bsh[buf * BBUF_H + row * PITCH_H]);
#pragma unroll
    for (int r = 0; r < 2; r++) {
        int c = cq + 8 * r;
        cp16(sb + 16 * c, arow + 8 * c);
    }
}
__device__ __forceinline__ void g1_fill_w(unsigned* Wf, int buf, const uint4* wsrc,
                                          int slice_stride_u4, int tid) {
    unsigned sw = smem_u32(&Wf[buf * WFRAG]);
#pragma unroll
    for (int r = 0; r < 2; r++) {
        int fidx = tid + r * 256;
        int sl = fidx >> 8, rem = fidx & 255;
        cp16(sw + 16 * fidx, wsrc + sl * slice_stride_u4 + rem);
    }
}
__device__ __forceinline__ void g1_compute(const __half* Bsh, const unsigned* Wf,
                                           int buf, int warp_m, int warp_n,
                                           int lane, float acc[4][4][4]) {
    const uint4*  Wf4 = (const uint4*)&Wf[buf * WFRAG];
    const __half* Bsb = &Bsh[buf * BBUF_H];
    unsigned baddr = smem_u32(Bsb + (lane & 15) * PITCH_H + warp_n * 32 + ((lane >> 4) << 3));
#pragma unroll
    for (int ks = 0; ks < 2; ks++) {
        uint4 a[4];
#pragma unroll
        for (int mi = 0; mi < 4; mi++)
            a[mi] = Wf4[(ks * 8 + warp_m * 4 + mi) * 32 + lane];
        unsigned b0[4], b1[4];
        unsigned ksa = baddr + ks * 16 * PITCH_H * 2;
        ldsm4t(b0[0], b1[0], b0[1], b1[1], ksa);
        ldsm4t(b0[2], b1[2], b0[3], b1[3], ksa + 32);
#pragma unroll
        for (int mi = 0; mi < 4; mi++)
#pragma unroll
            for (int ni = 0; ni < 4; ni++)
                mma16(acc[mi][ni][0], acc[mi][ni][1], acc[mi][ni][2], acc[mi][ni][3],
                      a[mi].x, a[mi].y, a[mi].z, a[mi].w, b0[ni], b1[ni]);
    }
}

__global__ __launch_bounds__(256, 3)
void gemm1_kernel() {
    extern __shared__ char smem[];
    __half* Bsh = (__half*)smem;
    unsigned* Wf = (unsigned*)(smem + NSTAGE * BBUF_H * 2);

    int tid = threadIdx.x, lane = tid & 31, wid = tid >> 5;
    int warp_m = wid >> 2, warp_n = wid & 3;
    int g = lane >> 2, tig = lane & 3;
    int b = blockIdx.z, t0 = blockIdx.x * 128;
    int mt0 = blockIdx.y * 8;
    int m0 = blockIdx.y * 128;

    const int row = tid >> 3, cq = tid & 7;
    const int NCH = INDIM / KC;   // 4
    const uint4* wbase = (const uint4*)g_wf1h;

    auto fill1 = [&](int c) {
        const __half* arow = g_xt + ((size_t)b * INDIM + c * KC + row) * TLEN + t0;
        g1_fill_b(Bsh, c % NSTAGE, arow, row, cq);
        g1_fill_w(Wf, c % NSTAGE, wbase + (size_t)((2 * c) * 32 + mt0) * 32, 32 * 32, tid);
        cp_commit();
    };

    fill1(0);
    fill1(1);

    float acc[4][4][4];
#pragma unroll
    for (int mi = 0; mi < 4; mi++)
#pragma unroll
        for (int ni = 0; ni < 4; ni++)
#pragma unroll
            for (int q = 0; q < 4; q++) acc[mi][ni][q] = 0.f;

    for (int c = 0; c < NCH; c++) {
        if (c + 2 < NCH) cp_wait1(); else cp_wait0();
        __syncthreads();
        if (c + 2 < NCH) fill1(c + 2);
        g1_compute(Bsh, Wf, c % NSTAGE, warp_m, warp_n, lane, acc);
    }

    __half* dst = (m0 < 256) ? g_bx_re : g_bx_im;
    int hbase = m0 & 255;
#pragma unroll
    for (int mi = 0; mi < 4; mi++) {
        int h = hbase + warp_m * 64 + mi * 16 + g;
#pragma unroll
        for (int ni = 0; ni < 4; ni++) {
            int t = t0 + warp_n * 32 + ni * 8 + 2 * tig;
            ((unsigned*)dst)[(((size_t)b * HID + h) * TLEN + t) >> 1] =
                pack_h2(acc[mi][ni][0], acc[mi][ni][1]);
            ((unsigned*)dst)[(((size_t)b * HID + h + 8) * TLEN + t) >> 1] =
                pack_h2(acc[mi][ni][2], acc[mi][ni][3]);
        }
    }
}

// ---------------------------------------------------------------------------
// Scan: inclusive complex scan over t, 8 elems/lane, fp16 I/O, fp32 math.
// ---------------------------------------------------------------------------
__global__ __launch_bounds__(256)
void scan_kernel() {
    int wg   = (blockIdx.x * blockDim.x + threadIdx.x) >> 5;
    int lane = threadIdx.x & 31;
    if (wg >= BATCH * HID) return;
    int b = wg >> 8;
    int h = wg & (HID - 1);

    float lr[8], li[8];
    lr[0] = g_lam_re[h]; li[0] = g_lam_im[h];
#pragma unroll
    for (int k = 1; k < 8; k++) {
        lr[k] = lr[k-1] * lr[0] - li[k-1] * li[0];
        li[k] = lr[k-1] * li[0] + li[k-1] * lr[0];
    }
    float pdr[5], pdi[5];
    pdr[0] = lr[7]; pdi[0] = li[7];
#pragma unroll
    for (int s = 1; s < 5; s++) {
        pdr[s] = pdr[s-1] * pdr[s-1] - pdi[s-1] * pdi[s-1];
        pdi[s] = 2.f * pdr[s-1] * pdi[s-1];
    }
    float mag = g_mag[h], th = g_th[h];
    float mp  = powf(mag, 8.f * (float)lane);
    float sa, ca;
    sincosf(th * 8.f * (float)lane, &sa, &ca);
    float c8r = mp * ca, c8i = mp * sa;

    float ccr = 0.f, cci = 0.f;
    size_t base = ((size_t)b * HID + h) * TLEN;
    const int NCH = TLEN / 256;   // 16

    size_t off = base + (size_t)lane * 8;
    uint4 vr = *(const uint4*)&g_bx_re[off];
    uint4 vi = *(const uint4*)&g_bx_im[off];

    for (int c = 0; c < NCH; c++) {
        float xr[8], xi[8];
        {
            float2 f;
            f = __half22float2(*(__half2*)&vr.x); xr[0] = f.x; xr[1] = f.y;
            f = __half22float2(*(__half2*)&vr.y); xr[2] = f.x; xr[3] = f.y;
            f = __half22float2(*(__half2*)&vr.z); xr[4] = f.x; xr[5] = f.y;
            f = __half22float2(*(__half2*)&vr.w); xr[6] = f.x; xr[7] = f.y;
            f = __half22float2(*(__half2*)&vi.x); xi[0] = f.x; xi[1] = f.y;
            f = __half22float2(*(__half2*)&vi.y); xi[2] = f.x; xi[3] = f.y;
            f = __half22float2(*(__half2*)&vi.z); xi[4] = f.x; xi[5] = f.y;
            f = __half22float2(*(__half2*)&vi.w); xi[6] = f.x; xi[7] = f.y;
        }
        size_t coff = off;
        if (c + 1 < NCH) {
            off += 256;
            vr = *(const uint4*)&g_bx_re[off];
            vi = *(const uint4*)&g_bx_im[off];
        }

        float yr[8], yi[8];
        yr[0] = xr[0]; yi[0] = xi[0];
#pragma unroll
        for (int k = 1; k < 8; k++) {
            yr[k] = xr[k] + lr[0] * yr[k-1] - li[0] * yi[k-1];
            yi[k] = xi[k] + lr[0] * yi[k-1] + li[0] * yr[k-1];
        }

        float sr = yr[7], si = yi[7];
#pragma unroll
        for (int s = 0; s < 5; s++) {
            int d = 1 << s;
            float tr = __shfl_up_sync(0xffffffffu, sr, d);
            float ti = __shfl_up_sync(0xffffffffu, si, d);
            if (lane >= d) {
                sr += pdr[s] * tr - pdi[s] * ti;
                si += pdr[s] * ti + pdi[s] * tr;
            }
        }
        float qr = __shfl_up_sync(0xffffffffu, sr, 1);
        float qi = __shfl_up_sync(0xffffffffu, si, 1);
        if (lane == 0) { qr = 0.f; qi = 0.f; }
        qr += c8r * ccr - c8i * cci;
        qi += c8r * cci + c8i * ccr;

        float or_[8], oi_[8];
#pragma unroll
        for (int k = 0; k < 8; k++) {
            or_[k] = yr[k] + lr[k] * qr - li[k] * qi;
            oi_[k] = yi[k] + lr[k] * qi + li[k] * qr;
        }

        ccr = __shfl_sync(0xffffffffu, or_[7], 31);
        cci = __shfl_sync(0xffffffffu, oi_[7], 31);

        uint4 wr, wi;
        wr.x = pack_h2(or_[0], or_[1]); wr.y = pack_h2(or_[2], or_[3]);
        wr.z = pack_h2(or_[4], or_[5]); wr.w = pack_h2(or_[6], or_[7]);
        wi.x = pack_h2(oi_[0], oi_[1]); wi.y = pack_h2(oi_[2], oi_[3]);
        wi.z = pack_h2(oi_[4], oi_[5]); wi.w = pack_h2(oi_[6], oi_[7]);
        *(uint4*)&g_bx_re[coff] = wr;
        *(uint4*)&g_bx_im[coff] = wi;
    }
}

// ---------------------------------------------------------------------------
// GEMM2 (128 threads, tile 128o x 64t, grid 64x8=512 for SM balance)
// 4 warps: warp_m = wid>>1 (2), warp_n = wid&1 (2); warp tile m64 n32.
// ---------------------------------------------------------------------------
__device__ __forceinline__ void g2_fill_b(__half* Bsh, int buf, const __half* arow,
                                          int row, int cq) {
    unsigned sb = smem_u32(&Bsh[buf * BBUF2_H + row * PITCH2_H]);
#pragma unroll
    for (int r = 0; r < 2; r++) {
        int c = cq + 4 * r;
        cp16(sb + 16 * c, arow + 8 * c);
    }
}
__device__ __forceinline__ void g2_fill_w(unsigned* Wf, int buf, const uint4* wsrc,
                                          int tid) {
    unsigned sw = smem_u32(&Wf[buf * WFRAG]);
#pragma unroll
    for (int r = 0; r < 4; r++) {
        int fidx = tid + r * 128;
        cp16(sw + 16 * fidx, wsrc + fidx);
    }
}
__device__ __forceinline__ void g2_compute(const __half* Bsh, const unsigned* Wf,
                                           int buf, int warp_m, int warp_n,
                                           int lane, float acc[4][4][4]) {
    const uint4*  Wf4 = (const uint4*)&Wf[buf * WFRAG];
    const __half* Bsb = &Bsh[buf * BBUF2_H];
    unsigned baddr = smem_u32(Bsb + (lane & 15) * PITCH2_H + warp_n * 32 + ((lane >> 4) << 3));
#pragma unroll
    for (int ks = 0; ks < 2; ks++) {
        uint4 a[4];
#pragma unroll
        for (int mi = 0; mi < 4; mi++)
            a[mi] = Wf4[(ks * 8 + warp_m * 4 + mi) * 32 + lane];
        unsigned b0[4], b1[4];
        unsigned ksa = baddr + ks * 16 * PITCH2_H * 2;
        ldsm4t(b0[0], b1[0], b0[1], b1[1], ksa);
        ldsm4t(b0[2], b1[2], b0[3], b1[3], ksa + 32);
#pragma unroll
        for (int mi = 0; mi < 4; mi++)
#pragma unroll
            for (int ni = 0; ni < 4; ni++)
                mma16(acc[mi][ni][0], acc[mi][ni][1], acc[mi][ni][2], acc[mi][ni][3],
                      a[mi].x, a[mi].y, a[mi].z, a[mi].w, b0[ni], b1[ni]);
    }
}

__global__ __launch_bounds__(128)
void gemm2_kernel(float* __restrict__ Y) {
    extern __shared__ char smem[];
    __half* Bsh = (__half*)smem;
    unsigned* Wf = (unsigned*)(smem + NSTAGE * BBUF2_H * 2);

    int tid = threadIdx.x, lane = tid & 31, wid = tid >> 5;
    int warp_m = wid >> 1, warp_n = wid & 1;
    int g = lane >> 2, tig = lane & 3;
    int b = blockIdx.y, t0 = blockIdx.x * 64;

    float acc[4][4][4];
#pragma unroll
    for (int mi = 0; mi < 4; mi++)
#pragma unroll
        for (int ni = 0; ni < 4; ni++)
#pragma unroll
            for (int q = 0; q < 4; q++) acc[mi][ni][q] = 0.f;

    const int row = tid >> 2, cq = tid & 3;
    const int NCH = 640 / KC;   // 20
    const uint4* wbase = (const uint4*)g_wf2h;

    auto arow_of = [&](int k) -> const __half* {
        if (k < 256)      return g_bx_re + ((size_t)b * HID + k) * TLEN + t0;
        else if (k < 512) return g_bx_im + ((size_t)b * HID + (k - 256)) * TLEN + t0;
        else              return g_xt   + ((size_t)b * INDIM + (k - 512)) * TLEN + t0;
    };
    auto fill2 = [&](int c) {
        g2_fill_b(Bsh, c % NSTAGE, arow_of(c * KC + row), row, cq);
        g2_fill_w(Wf, c % NSTAGE, wbase + (size_t)c * 512, tid);
        cp_commit();
    };

    fill2(0);
    fill2(1);

    for (int c = 0; c < NCH; c++) {
        if (c + 2 < NCH) cp_wait1(); else cp_wait0();
        __syncthreads();
        if (c + 2 < NCH) fill2(c + 2);
        g2_compute(Bsh, Wf, c % NSTAGE, warp_m, warp_n, lane, acc);
    }

#pragma unroll
    for (int mi = 0; mi < 4; mi++) {
        int o = warp_m * 64 + mi * 16 + g;
#pragma unroll
        for (int ni = 0; ni < 4; ni++) {
            int t = t0 + warp_n * 32 + ni * 8 + 2 * tig;
            size_t y0 = ((size_t)b * TLEN + t) * OUTDIM;
            size_t y1 = ((size_t)b * TLEN + t + 1) * OUTDIM;
            Y[y0 + o]     = acc[mi][ni][0];
            Y[y1 + o]     = acc[mi][ni][1];
            Y[y0 + o + 8] = acc[mi][ni][2];
            Y[y1 + o + 8] = acc[mi][ni][3];
        }
    }
}

// ---------------------------------------------------------------------------
extern "C" void kernel_launch(void* const* d_in, const int* in_sizes, int n_in,
                              void* d_out, int out_size) {
    const float* X         = (const float*)d_in[0];
    const float* nu_log    = (const float*)d_in[1];
    const float* theta_log = (const float*)d_in[2];
    const float* B_re      = (const float*)d_in[3];
    const float* B_im      = (const float*)d_in[4];
    const float* C_re      = (const float*)d_in[5];
    const float* C_im      = (const float*)d_in[6];
    const float* D         = (const float*)d_in[7];
    float* Y = (float*)d_out;

    cudaFuncSetAttribute(gemm1_kernel, cudaFuncAttributeMaxDynamicSharedMemorySize, SMEM_G1);
    cudaFuncSetAttribute(gemm2_kernel, cudaFuncAttributeMaxDynamicSharedMemorySize, SMEM_G2);

    prep_all_kernel<<<NB_ALL, 256>>>(X, nu_log, theta_log, B_re, B_im, C_re, C_im, D);

    dim3 g1(TLEN / 128, 4, BATCH);
    gemm1_kernel<<<g1, 256, SMEM_G1>>>();

    scan_kernel<<<(BATCH * HID * 32) / 256, 256>>>();

    dim3 g2(TLEN / 64, BATCH);
    gemm2_kernel<<<g2, 128, SMEM_G2>>>(Y);
}

// round 15
// speedup vs baseline: 1.0580x; 1.0580x over previous
#include <cuda_runtime.h>
#include <cuda_fp16.h>
#include <cstdint>

#define BATCH 8
#define TLEN 4096
#define INDIM 128
#define OUTDIM 128
#define HID 256
#define PITCH_H 136            // halves per t-data smem row (272B)
// gemm1: KC=32, 3 stages (round-13 proven config)
#define KC1 32
#define BBUF1_H (KC1 * PITCH_H)      // 4352 halves
#define WFRAG1 2048                  // frag words per stage
#define NSTAGE1 3
#define SMEM_G1 (NSTAGE1 * (BBUF1_H * 2 + WFRAG1 * 4))   // 50688
// gemm2: KC=64, 2 stages (halved barrier count)
#define KC2 64
#define BBUF2_H (KC2 * PITCH_H)      // 8704 halves
#define WFRAG2 4096                  // frag words per stage (4 K16)
#define NSTAGE2 2
#define SMEM_G2 (NSTAGE2 * (BBUF2_H * 2 + WFRAG2 * 4))   // 67584

// ---- scratch (device globals: allocation-free rule) ----
__device__ float g_lam_re[HID];
__device__ float g_lam_im[HID];
__device__ float g_mag[HID];
__device__ float g_th[HID];
__device__ __half g_bx_re[(size_t)BATCH * HID * TLEN];   // [b][h][t] fp16
__device__ __half g_bx_im[(size_t)BATCH * HID * TLEN];
__device__ __half g_xt[(size_t)BATCH * INDIM * TLEN];    // [b][i][t] fp16
// fp16 weight fragments, mma m16n8k16 order: [K16][mt][lane][4 words]
__device__ unsigned g_wf1h[8 * 32 * 32 * 4];             // gemm1: M=512, K=128
__device__ unsigned g_wf2h[40 * 8 * 32 * 4];             // gemm2: M=128, K=640

// ---- helpers ----
__device__ __forceinline__ unsigned pack_h2(float lo, float hi) {
    unsigned d;
    asm("cvt.rn.f16x2.f32 %0, %1, %2;" : "=r"(d) : "f"(hi), "f"(lo));
    return d;
}
__device__ __forceinline__ void mma16(float& d0, float& d1, float& d2, float& d3,
                                      unsigned a0, unsigned a1, unsigned a2, unsigned a3,
                                      unsigned b0, unsigned b1) {
    asm("mma.sync.aligned.m16n8k16.row.col.f32.f16.f16.f32 "
        "{%0,%1,%2,%3}, {%4,%5,%6,%7}, {%8,%9}, {%0,%1,%2,%3};"
        : "+f"(d0), "+f"(d1), "+f"(d2), "+f"(d3)
        : "r"(a0), "r"(a1), "r"(a2), "r"(a3), "r"(b0), "r"(b1));
}
__device__ __forceinline__ void ldsm4t(unsigned& r0, unsigned& r1,
                                       unsigned& r2, unsigned& r3, unsigned addr) {
    asm volatile("ldmatrix.sync.aligned.m8n8.x4.trans.shared.b16 {%0,%1,%2,%3}, [%4];"
        : "=r"(r0), "=r"(r1), "=r"(r2), "=r"(r3) : "r"(addr));
}
__device__ __forceinline__ unsigned smem_u32(const void* p) {
    return (unsigned)__cvta_generic_to_shared(p);
}
__device__ __forceinline__ void cp16(unsigned s, const void* g) {
    asm volatile("cp.async.cg.shared.global [%0], [%1], 16;" :: "r"(s), "l"(g));
}
__device__ __forceinline__ void cp_commit() { asm volatile("cp.async.commit_group;"); }
__device__ __forceinline__ void cp_wait1()  { asm volatile("cp.async.wait_group 1;"); }
__device__ __forceinline__ void cp_wait0()  { asm volatile("cp.async.wait_group 0;"); }

// ---------------------------------------------------------------------------
// prep_all: X transpose (fp16 packed) + fp16 weight fragments + params
// ---------------------------------------------------------------------------
#define WF1H_N (8 * 32 * 32 * 4)    // 32768 words
#define WF2H_N (40 * 8 * 32 * 4)    // 40960 words
#define NB_XT 4096
#define NB_W  ((WF1H_N + WF2H_N) / 256)   // 288
#define NB_ALL (NB_XT + NB_W + 1)

__global__ __launch_bounds__(256)
void prep_all_kernel(const float* __restrict__ X,
                     const float* __restrict__ nu_log,
                     const float* __restrict__ theta_log,
                     const float* __restrict__ Bre, const float* __restrict__ Bim,
                     const float* __restrict__ Cre, const float* __restrict__ Cim,
                     const float* __restrict__ Dm) {
    __shared__ float tile[32][33];
    int bid = blockIdx.x;
    int tid = threadIdx.x;

    if (bid < NB_XT) {
        int t0 = (bid & 127) * 32;
        int i0 = ((bid >> 7) & 3) * 32;
        int b  = bid >> 9;
#pragma unroll
        for (int r = 0; r < 4; r++) {
            int idx = tid + 256 * r;
            int tl = idx >> 5, il = idx & 31;
            tile[tl][il] = X[((size_t)b * TLEN + t0 + tl) * INDIM + i0 + il];
        }
        __syncthreads();
#pragma unroll
        for (int r = 0; r < 2; r++) {
            int idx = tid + 256 * r;
            int il = idx >> 4, tp = idx & 15;
            unsigned w = pack_h2(tile[2 * tp][il], tile[2 * tp + 1][il]);
            ((unsigned*)g_xt)[(((size_t)b * INDIM + i0 + il) * TLEN + t0) / 2 + tp] = w;
        }
    } else if (bid < NB_XT + NB_W) {
        int idx = (bid - NB_XT) * 256 + tid;
        if (idx < WF1H_N) {
            int j = idx & 3, lane = (idx >> 2) & 31, mt = (idx >> 7) & 31, K16 = idx >> 12;
            int g = lane >> 2, tig = lane & 3;
            int m = mt * 16 + g + (j & 1) * 8;
            int k0 = K16 * 16 + 2 * tig + (j >> 1) * 8;
            int h = m & 255;
            float mag = expf(-expf(nu_log[h]));
            float gam = sqrtf(fmaxf(1.0f - mag * mag, 0.0f));
            const float* wrow = (m < 256) ? &Bre[(size_t)h * INDIM] : &Bim[(size_t)h * INDIM];
            g_wf1h[idx] = pack_h2(gam * wrow[k0], gam * wrow[k0 + 1]);
        } else {
            int e = idx - WF1H_N;
            int j = e & 3, lane = (e >> 2) & 31, mt = (e >> 7) & 7, K16 = e >> 10;
            int g = lane >> 2, tig = lane & 3;
            int o = mt * 16 + g + (j & 1) * 8;
            int k0 = K16 * 16 + 2 * tig + (j >> 1) * 8;
            float v0, v1;
            if (k0 < 256)      { v0 =  Cre[(size_t)o * HID + k0];         v1 =  Cre[(size_t)o * HID + k0 + 1]; }
            else if (k0 < 512) { v0 = -Cim[(size_t)o * HID + k0 - 256];   v1 = -Cim[(size_t)o * HID + k0 - 255]; }
            else               { v0 =  Dm[(size_t)o * INDIM + k0 - 512];  v1 =  Dm[(size_t)o * INDIM + k0 - 511]; }
            g_wf2h[e] = pack_h2(v0, v1);
        }
    } else {
        int h = tid;
        if (h < HID) {
            float mag = expf(-expf(nu_log[h]));
            float th  = expf(theta_log[h]);
            g_mag[h] = mag;
            g_th[h]  = th;
            g_lam_re[h] = mag * cosf(th);
            g_lam_im[h] = mag * sinf(th);
        }
    }
}

// ---------------------------------------------------------------------------
// GEMM1 (round-13 config: 256 threads, 128m x 128t, KC=32, 3 stages)
// ---------------------------------------------------------------------------
__device__ __forceinline__ void g1_fill_b(__half* Bsh, int buf, const __half* arow,
                                          int row, int cq) {
    unsigned sb = smem_u32(&Bsh[buf * BBUF1_H + row * PITCH_H]);
#pragma unroll
    for (int r = 0; r < 2; r++) {
        int c = cq + 8 * r;
        cp16(sb + 16 * c, arow + 8 * c);
    }
}
__device__ __forceinline__ void g1_fill_w(unsigned* Wf, int buf, const uint4* wsrc,
                                          int slice_stride_u4, int tid) {
    unsigned sw = smem_u32(&Wf[buf * WFRAG1]);
#pragma unroll
    for (int r = 0; r < 2; r++) {
        int fidx = tid + r * 256;
        int sl = fidx >> 8, rem = fidx & 255;
        cp16(sw + 16 * fidx, wsrc + sl * slice_stride_u4 + rem);
    }
}
__device__ __forceinline__ void g1_compute(const __half* Bsh, const unsigned* Wf,
                                           int buf, int warp_m, int warp_n,
                                           int lane, float acc[4][4][4]) {
    const uint4*  Wf4 = (const uint4*)&Wf[buf * WFRAG1];
    const __half* Bsb = &Bsh[buf * BBUF1_H];
    unsigned baddr = smem_u32(Bsb + (lane & 15) * PITCH_H + warp_n * 32 + ((lane >> 4) << 3));
#pragma unroll
    for (int ks = 0; ks < 2; ks++) {
        uint4 a[4];
#pragma unroll
        for (int mi = 0; mi < 4; mi++)
            a[mi] = Wf4[(ks * 8 + warp_m * 4 + mi) * 32 + lane];
        unsigned b0[4], b1[4];
        unsigned ksa = baddr + ks * 16 * PITCH_H * 2;
        ldsm4t(b0[0], b1[0], b0[1], b1[1], ksa);
        ldsm4t(b0[2], b1[2], b0[3], b1[3], ksa + 32);
#pragma unroll
        for (int mi = 0; mi < 4; mi++)
#pragma unroll
            for (int ni = 0; ni < 4; ni++)
                mma16(acc[mi][ni][0], acc[mi][ni][1], acc[mi][ni][2], acc[mi][ni][3],
                      a[mi].x, a[mi].y, a[mi].z, a[mi].w, b0[ni], b1[ni]);
    }
}

__global__ __launch_bounds__(256)
void gemm1_kernel() {
    extern __shared__ char smem[];
    __half* Bsh = (__half*)smem;
    unsigned* Wf = (unsigned*)(smem + NSTAGE1 * BBUF1_H * 2);

    int tid = threadIdx.x, lane = tid & 31, wid = tid >> 5;
    int warp_m = wid >> 2, warp_n = wid & 3;
    int g = lane >> 2, tig = lane & 3;
    int b = blockIdx.z, t0 = blockIdx.x * 128;
    int mt0 = blockIdx.y * 8;
    int m0 = blockIdx.y * 128;

    const int row = tid >> 3, cq = tid & 7;
    const int NCH = INDIM / KC1;   // 4
    const uint4* wbase = (const uint4*)g_wf1h;

    auto fill1 = [&](int c) {
        const __half* arow = g_xt + ((size_t)b * INDIM + c * KC1 + row) * TLEN + t0;
        g1_fill_b(Bsh, c % NSTAGE1, arow, row, cq);
        g1_fill_w(Wf, c % NSTAGE1, wbase + (size_t)((2 * c) * 32 + mt0) * 32, 32 * 32, tid);
        cp_commit();
    };

    fill1(0);
    fill1(1);

    float acc[4][4][4];
#pragma unroll
    for (int mi = 0; mi < 4; mi++)
#pragma unroll
        for (int ni = 0; ni < 4; ni++)
#pragma unroll
            for (int q = 0; q < 4; q++) acc[mi][ni][q] = 0.f;

    for (int c = 0; c < NCH; c++) {
        if (c + 2 < NCH) cp_wait1(); else cp_wait0();
        __syncthreads();
        if (c + 2 < NCH) fill1(c + 2);
        g1_compute(Bsh, Wf, c % NSTAGE1, warp_m, warp_n, lane, acc);
    }

    __half* dst = (m0 < 256) ? g_bx_re : g_bx_im;
    int hbase = m0 & 255;
#pragma unroll
    for (int mi = 0; mi < 4; mi++) {
        int h = hbase + warp_m * 64 + mi * 16 + g;
#pragma unroll
        for (int ni = 0; ni < 4; ni++) {
            int t = t0 + warp_n * 32 + ni * 8 + 2 * tig;
            ((unsigned*)dst)[(((size_t)b * HID + h) * TLEN + t) >> 1] =
                pack_h2(acc[mi][ni][0], acc[mi][ni][1]);
            ((unsigned*)dst)[(((size_t)b * HID + h + 8) * TLEN + t) >> 1] =
                pack_h2(acc[mi][ni][2], acc[mi][ni][3]);
        }
    }
}

// ---------------------------------------------------------------------------
// Scan: inclusive complex scan over t, 8 elems/lane, fp16 I/O, fp32 math.
// ---------------------------------------------------------------------------
__global__ __launch_bounds__(256)
void scan_kernel() {
    int wg   = (blockIdx.x * blockDim.x + threadIdx.x) >> 5;
    int lane = threadIdx.x & 31;
    if (wg >= BATCH * HID) return;
    int b = wg >> 8;
    int h = wg & (HID - 1);

    float lr[8], li[8];
    lr[0] = g_lam_re[h]; li[0] = g_lam_im[h];
#pragma unroll
    for (int k = 1; k < 8; k++) {
        lr[k] = lr[k-1] * lr[0] - li[k-1] * li[0];
        li[k] = lr[k-1] * li[0] + li[k-1] * lr[0];
    }
    float pdr[5], pdi[5];
    pdr[0] = lr[7]; pdi[0] = li[7];
#pragma unroll
    for (int s = 1; s < 5; s++) {
        pdr[s] = pdr[s-1] * pdr[s-1] - pdi[s-1] * pdi[s-1];
        pdi[s] = 2.f * pdr[s-1] * pdi[s-1];
    }
    float mag = g_mag[h], th = g_th[h];
    float mp  = powf(mag, 8.f * (float)lane);
    float sa, ca;
    sincosf(th * 8.f * (float)lane, &sa, &ca);
    float c8r = mp * ca, c8i = mp * sa;

    float ccr = 0.f, cci = 0.f;
    size_t base = ((size_t)b * HID + h) * TLEN;
    const int NCH = TLEN / 256;   // 16

    size_t off = base + (size_t)lane * 8;
    uint4 vr = *(const uint4*)&g_bx_re[off];
    uint4 vi = *(const uint4*)&g_bx_im[off];

    for (int c = 0; c < NCH; c++) {
        float xr[8], xi[8];
        {
            float2 f;
            f = __half22float2(*(__half2*)&vr.x); xr[0] = f.x; xr[1] = f.y;
            f = __half22float2(*(__half2*)&vr.y); xr[2] = f.x; xr[3] = f.y;
            f = __half22float2(*(__half2*)&vr.z); xr[4] = f.x; xr[5] = f.y;
            f = __half22float2(*(__half2*)&vr.w); xr[6] = f.x; xr[7] = f.y;
            f = __half22float2(*(__half2*)&vi.x); xi[0] = f.x; xi[1] = f.y;
            f = __half22float2(*(__half2*)&vi.y); xi[2] = f.x; xi[3] = f.y;
            f = __half22float2(*(__half2*)&vi.z); xi[4] = f.x; xi[5] = f.y;
            f = __half22float2(*(__half2*)&vi.w); xi[6] = f.x; xi[7] = f.y;
        }
        size_t coff = off;
        if (c + 1 < NCH) {
            off += 256;
            vr = *(const uint4*)&g_bx_re[off];
            vi = *(const uint4*)&g_bx_im[off];
        }

        float yr[8], yi[8];
        yr[0] = xr[0]; yi[0] = xi[0];
#pragma unroll
        for (int k = 1; k < 8; k++) {
            yr[k] = xr[k] + lr[0] * yr[k-1] - li[0] * yi[k-1];
            yi[k] = xi[k] + lr[0] * yi[k-1] + li[0] * yr[k-1];
        }

        float sr = yr[7], si = yi[7];
#pragma unroll
        for (int s = 0; s < 5; s++) {
            int d = 1 << s;
            float tr = __shfl_up_sync(0xffffffffu, sr, d);
            float ti = __shfl_up_sync(0xffffffffu, si, d);
            if (lane >= d) {
                sr += pdr[s] * tr - pdi[s] * ti;
                si += pdr[s] * ti + pdi[s] * tr;
            }
        }
        float qr = __shfl_up_sync(0xffffffffu, sr, 1);
        float qi = __shfl_up_sync(0xffffffffu, si, 1);
        if (lane == 0) { qr = 0.f; qi = 0.f; }
        qr += c8r * ccr - c8i * cci;
        qi += c8r * cci + c8i * ccr;

        float or_[8], oi_[8];
#pragma unroll
        for (int k = 0; k < 8; k++) {
            or_[k] = yr[k] + lr[k] * qr - li[k] * qi;
            oi_[k] = yi[k] + lr[k] * qi + li[k] * qr;
        }

        ccr = __shfl_sync(0xffffffffu, or_[7], 31);
        cci = __shfl_sync(0xffffffffu, oi_[7], 31);

        uint4 wr, wi;
        wr.x = pack_h2(or_[0], or_[1]); wr.y = pack_h2(or_[2], or_[3]);
        wr.z = pack_h2(or_[4], or_[5]); wr.w = pack_h2(or_[6], or_[7]);
        wi.x = pack_h2(oi_[0], oi_[1]); wi.y = pack_h2(oi_[2], oi_[3]);
        wi.z = pack_h2(oi_[4], oi_[5]); wi.w = pack_h2(oi_[6], oi_[7]);
        *(uint4*)&g_bx_re[coff] = wr;
        *(uint4*)&g_bx_im[coff] = wi;
    }
}

// ---------------------------------------------------------------------------
// GEMM2: 256 threads, 128o x 128t, KC=64 (4 k16 steps/chunk), 2 stages,
// 10 chunks total — halved barrier/wait count vs round 13.
// ---------------------------------------------------------------------------
__device__ __forceinline__ void g2_fill_b(__half* Bsh, int buf, int b, int kbase,
                                          int t0, int row, int cq) {
    // row in 0..63, 4 cp16 per thread (16 per row)
    int k = kbase + row;
    const __half* arow;
    if (k < 256)      arow = g_bx_re + ((size_t)b * HID + k) * TLEN + t0;
    else if (k < 512) arow = g_bx_im + ((size_t)b * HID + (k - 256)) * TLEN + t0;
    else              arow = g_xt   + ((size_t)b * INDIM + (k - 512)) * TLEN + t0;
    unsigned sb = smem_u32(&Bsh[buf * BBUF2_H + row * PITCH_H]);
#pragma unroll
    for (int r = 0; r < 4; r++) {
        int c = cq + 4 * r;
        cp16(sb + 16 * c, arow + 8 * c);
    }
}
__device__ __forceinline__ void g2_fill_w(unsigned* Wf, int buf, const uint4* wsrc,
                                          int tid) {
    unsigned sw = smem_u32(&Wf[buf * WFRAG2]);
#pragma unroll
    for (int r = 0; r < 4; r++) {
        int fidx = tid + r * 256;
        cp16(sw + 16 * fidx, wsrc + fidx);
    }
}
__device__ __forceinline__ void g2_compute(const __half* Bsh, const unsigned* Wf,
                                           int buf, int warp_m, int warp_n,
                                           int lane, float acc[4][4][4]) {
    const uint4*  Wf4 = (const uint4*)&Wf[buf * WFRAG2];
    const __half* Bsb = &Bsh[buf * BBUF2_H];
    unsigned baddr = smem_u32(Bsb + (lane & 15) * PITCH_H + warp_n * 32 + ((lane >> 4) << 3));
#pragma unroll
    for (int ks = 0; ks < 4; ks++) {
        uint4 a[4];
#pragma unroll
        for (int mi = 0; mi < 4; mi++)
            a[mi] = Wf4[(ks * 8 + warp_m * 4 + mi) * 32 + lane];
        unsigned b0[4], b1[4];
        unsigned ksa = baddr + ks * 16 * PITCH_H * 2;
        ldsm4t(b0[0], b1[0], b0[1], b1[1], ksa);
        ldsm4t(b0[2], b1[2], b0[3], b1[3], ksa + 32);
#pragma unroll
        for (int mi = 0; mi < 4; mi++)
#pragma unroll
            for (int ni = 0; ni < 4; ni++)
                mma16(acc[mi][ni][0], acc[mi][ni][1], acc[mi][ni][2], acc[mi][ni][3],
                      a[mi].x, a[mi].y, a[mi].z, a[mi].w, b0[ni], b1[ni]);
    }
}

__global__ __launch_bounds__(256)
void gemm2_kernel(float* __restrict__ Y) {
    extern __shared__ char smem[];
    __half* Bsh = (__half*)smem;
    unsigned* Wf = (unsigned*)(smem + NSTAGE2 * BBUF2_H * 2);

    int tid = threadIdx.x, lane = tid & 31, wid = tid >> 5;
    int warp_m = wid >> 2, warp_n = wid & 3;
    int g = lane >> 2, tig = lane & 3;
    int b = blockIdx.y, t0 = blockIdx.x * 128;

    float acc[4][4][4];
#pragma unroll
    for (int mi = 0; mi < 4; mi++)
#pragma unroll
        for (int ni = 0; ni < 4; ni++)
#pragma unroll
            for (int q = 0; q < 4; q++) acc[mi][ni][q] = 0.f;

    const int row = tid >> 2, cq = tid & 3;   // 64 rows, 4 threads/row
    const int NCH = 640 / KC2;   // 10
    const uint4* wbase = (const uint4*)g_wf2h;

    auto fill2 = [&](int c) {
        g2_fill_b(Bsh, c % NSTAGE2, b, c * KC2, t0, row, cq);
        g2_fill_w(Wf, c % NSTAGE2, wbase + (size_t)c * 1024, tid);
        cp_commit();
    };

    fill2(0);

    for (int c = 0; c < NCH; c++) {
        cp_wait0();
        __syncthreads();
        if (c + 1 < NCH) fill2(c + 1);
        g2_compute(Bsh, Wf, c % NSTAGE2, warp_m, warp_n, lane, acc);
    }

#pragma unroll
    for (int mi = 0; mi < 4; mi++) {
        int o = warp_m * 64 + mi * 16 + g;
#pragma unroll
        for (int ni = 0; ni < 4; ni++) {
            int t = t0 + warp_n * 32 + ni * 8 + 2 * tig;
            size_t y0 = ((size_t)b * TLEN + t) * OUTDIM;
            size_t y1 = ((size_t)b * TLEN + t + 1) * OUTDIM;
            Y[y0 + o]     = acc[mi][ni][0];
            Y[y1 + o]     = acc[mi][ni][1];
            Y[y0 + o + 8] = acc[mi][ni][2];
            Y[y1 + o + 8] = acc[mi][ni][3];
        }
    }
}

// ---------------------------------------------------------------------------
extern "C" void kernel_launch(void* const* d_in, const int* in_sizes, int n_in,
                              void* d_out, int out_size) {
    const float* X         = (const float*)d_in[0];
    const float* nu_log    = (const float*)d_in[1];
    const float* theta_log = (const float*)d_in[2];
    const float* B_re      = (const float*)d_in[3];
    const float* B_im      = (const float*)d_in[4];
    const float* C_re      = (const float*)d_in[5];
    const float* C_im      = (const float*)d_in[6];
    const float* D         = (const float*)d_in[7];
    float* Y = (float*)d_out;

    cudaFuncSetAttribute(gemm1_kernel, cudaFuncAttributeMaxDynamicSharedMemorySize, SMEM_G1);
    cudaFuncSetAttribute(gemm2_kernel, cudaFuncAttributeMaxDynamicSharedMemorySize, SMEM_G2);

    prep_all_kernel<<<NB_ALL, 256>>>(X, nu_log, theta_log, B_re, B_im, C_re, C_im, D);

    dim3 g1(TLEN / 128, 4, BATCH);
    gemm1_kernel<<<g1, 256, SMEM_G1>>>();

    scan_kernel<<<(BATCH * HID * 32) / 256, 256>>>();

    dim3 g2(TLEN / 128, BATCH);
    gemm2_kernel<<<g2, 256, SMEM_G2>>>(Y);
}